// round 3
// baseline (speedup 1.0000x reference)
#include <cuda_runtime.h>

#define NN   20000
#define EE   640000
#define ETOT (EE + NN)
#define DD   64
#define HH   8
#define LL   8

// ---------------- static scratch (no allocations allowed) ----------------
__device__ float g_cur[NN * DD];     // layer input/output ping buffer
__device__ float g_h[NN * DD];       // per-layer projection
__device__ float g_ssrc[NN * HH];
__device__ float g_sdst[NN * HH];
__device__ int   g_cnt[NN];
__device__ int   g_rowptr[NN + 1];
__device__ int   g_fill[NN];
__device__ int   g_csr[ETOT];
__device__ int   g_is64;

// ---------------- edge dtype detection ----------------
// If the harness kept int64, every 8-byte word holds a value in [0, NN).
// If it coerced to int32, an 8-byte word packs two indices -> >= 2^32 almost surely.
__global__ void detect_k(const void* __restrict__ ei) {
    const long long* p = (const long long*)ei;
    int ok = 1;
    for (int i = 0; i < 64; i++) {
        long long v = p[i];
        if (v < 0 || v >= NN) ok = 0;
    }
    g_is64 = ok;
}

__device__ __forceinline__ int edge_at(const void* ei, int is64, int idx) {
    return is64 ? (int)((const long long*)ei)[idx] : ((const int*)ei)[idx];
}

// ---------------- CSR build ----------------
__global__ void zero_k() {
    int i = blockIdx.x * blockDim.x + threadIdx.x;
    if (i < NN) g_cnt[i] = 0;
}

__global__ void count_k(const void* __restrict__ ei) {
    int e = blockIdx.x * blockDim.x + threadIdx.x;
    if (e >= ETOT) return;
    int is64 = g_is64;
    int dst = (e < EE) ? edge_at(ei, is64, EE + e) : (e - EE);
    if (dst >= 0 && dst < NN) atomicAdd(&g_cnt[dst], 1);
}

#define SCAN_T 1024
#define IPT 20   // 1024*20 = 20480 >= NN
__global__ void scan_k() {
    __shared__ int wsum[32];
    int t = threadIdx.x;
    int base = t * IPT;
    int loc[IPT];
    int run = 0;
#pragma unroll
    for (int i = 0; i < IPT; i++) {
        int idx = base + i;
        int v = (idx < NN) ? g_cnt[idx] : 0;
        loc[i] = run;
        run += v;
    }
    int lane = t & 31, w = t >> 5;
    int inc = run;
#pragma unroll
    for (int o = 1; o < 32; o <<= 1) {
        int u = __shfl_up_sync(0xffffffffu, inc, o);
        if (lane >= o) inc += u;
    }
    if (lane == 31) wsum[w] = inc;
    __syncthreads();
    if (w == 0) {
        int v = wsum[lane];
#pragma unroll
        for (int o = 1; o < 32; o <<= 1) {
            int u = __shfl_up_sync(0xffffffffu, v, o);
            if (lane >= o) v += u;
        }
        wsum[lane] = v;
    }
    __syncthreads();
    int warpoff = (w > 0) ? wsum[w - 1] : 0;
    int texcl = warpoff + inc - run;   // exclusive prefix at this thread's base
#pragma unroll
    for (int i = 0; i < IPT; i++) {
        int idx = base + i;
        if (idx < NN) {
            int val = texcl + loc[i];
            g_rowptr[idx] = val;
            g_fill[idx] = val;
        }
    }
    if (t == 0) g_rowptr[NN] = ETOT;
}

__global__ void scatter_k(const void* __restrict__ ei) {
    int e = blockIdx.x * blockDim.x + threadIdx.x;
    if (e >= ETOT) return;
    int is64 = g_is64;
    int src, dst;
    if (e < EE) { src = edge_at(ei, is64, e); dst = edge_at(ei, is64, EE + e); }
    else        { src = e - EE;               dst = e - EE; }
    if (dst < 0 || dst >= NN || src < 0 || src >= NN) return;
    int pos = atomicAdd(&g_fill[dst], 1);
    if (pos >= 0 && pos < ETOT) g_csr[pos] = src;
}

// ---------------- per-layer: projection h = cur @ W ----------------
// blockDim (64,4), 16 rows per block, each thread does 4 rows x 1 col.
__global__ void proj_k(const float* __restrict__ x, const float* __restrict__ W,
                       int first) {
    __shared__ float sW[64 * 64];
    __shared__ float sx[16][64];
    const float* src = first ? x : (const float*)g_cur;
    int tx = threadIdx.x, ty = threadIdx.y;
    int tid = ty * 64 + tx;
#pragma unroll
    for (int i = tid; i < 4096; i += 256) sW[i] = W[i];
    int row0 = blockIdx.x * 16;
#pragma unroll
    for (int r = ty; r < 16; r += 4) sx[r][tx] = src[(row0 + r) * DD + tx];
    __syncthreads();
    float acc0 = 0.f, acc1 = 0.f, acc2 = 0.f, acc3 = 0.f;
#pragma unroll
    for (int k = 0; k < 64; k++) {
        float wv = sW[k * 64 + tx];
        acc0 = fmaf(sx[ty + 0][k], wv, acc0);
        acc1 = fmaf(sx[ty + 4][k], wv, acc1);
        acc2 = fmaf(sx[ty + 8][k], wv, acc2);
        acc3 = fmaf(sx[ty + 12][k], wv, acc3);
    }
    g_h[(row0 + ty + 0) * DD + tx]  = acc0;
    g_h[(row0 + ty + 4) * DD + tx]  = acc1;
    g_h[(row0 + ty + 8) * DD + tx]  = acc2;
    g_h[(row0 + ty + 12) * DD + tx] = acc3;
}

// ---------------- per-layer: attention scores s_src/s_dst ----------------
__global__ void score_k(const float* __restrict__ asrc,
                        const float* __restrict__ adst) {
    int i = blockIdx.x * blockDim.x + threadIdx.x;
    if (i >= NN * HH) return;
    int hd = i & 7;
    int n = i >> 3;
    const float* hp = g_h + n * DD + hd * 8;
    const float* as = asrc + hd * 8;
    const float* ad = adst + hd * 8;
    float ss = 0.f, sdv = 0.f;
#pragma unroll
    for (int c = 0; c < 8; c++) {
        float v = hp[c];
        ss = fmaf(v, as[c], ss);
        sdv = fmaf(v, ad[c], sdv);
    }
    g_ssrc[i] = ss;
    g_sdst[i] = sdv;
}

__device__ __forceinline__ float lrelu(float e) { return e > 0.f ? e : 0.2f * e; }

// ---------------- per-layer: softmax-aggregate, one warp per dst node -----
__global__ void __launch_bounds__(256) gat_k(const float* __restrict__ bias,
                                             float* __restrict__ ext_out,
                                             int last) {
    int gw = (blockIdx.x * blockDim.x + threadIdx.x) >> 5;
    int lane = threadIdx.x & 31;
    if (gw >= NN) return;
    float* outp = last ? ext_out : (float*)g_cur;
    const float* h = (const float*)g_h;
    int beg = g_rowptr[gw], end = g_rowptr[gw + 1];

    float sd[HH];
#pragma unroll
    for (int k = 0; k < HH; k++) sd[k] = g_sdst[gw * HH + k];

    // pass 1: per-head max over incoming edges
    float mx[HH];
#pragma unroll
    for (int k = 0; k < HH; k++) mx[k] = -3.0e38f;
    for (int p = beg + lane; p < end; p += 32) {
        int s = g_csr[p];
        const float* sp = &g_ssrc[s * HH];
#pragma unroll
        for (int k = 0; k < HH; k++) {
            float e = lrelu(sp[k] + sd[k]);
            mx[k] = fmaxf(mx[k], e);
        }
    }
#pragma unroll
    for (int k = 0; k < HH; k++) {
#pragma unroll
        for (int o = 16; o > 0; o >>= 1)
            mx[k] = fmaxf(mx[k], __shfl_xor_sync(0xffffffffu, mx[k], o));
    }

    // pass 2: per-head exp-sum
    float z[HH];
#pragma unroll
    for (int k = 0; k < HH; k++) z[k] = 0.f;
    for (int p = beg + lane; p < end; p += 32) {
        int s = g_csr[p];
        const float* sp = &g_ssrc[s * HH];
#pragma unroll
        for (int k = 0; k < HH; k++) {
            float e = lrelu(sp[k] + sd[k]);
            z[k] += __expf(e - mx[k]);
        }
    }
#pragma unroll
    for (int k = 0; k < HH; k++) {
#pragma unroll
        for (int o = 16; o > 0; o >>= 1)
            z[k] += __shfl_xor_sync(0xffffffffu, z[k], o);
    }

    // per-lane head selection: lane owns output dims lane and lane+32
    int h0 = lane >> 3;       // head 0..3
    int h1 = h0 + 4;          // head 4..7
    float m0 = 0.f, m1 = 0.f, i0v = 0.f, i1v = 0.f, sd0 = 0.f, sd1 = 0.f;
#pragma unroll
    for (int k = 0; k < 4; k++) {
        if (h0 == k) {
            m0 = mx[k];     i0v = 1.f / (z[k] + 1e-16f);     sd0 = sd[k];
            m1 = mx[k + 4]; i1v = 1.f / (z[k + 4] + 1e-16f); sd1 = sd[k + 4];
        }
    }

    // pass 3: weighted gather (whole warp walks edge list; 2-edge unroll for MLP)
    float a0 = 0.f, a1 = 0.f;
    int p = beg;
    for (; p + 2 <= end; p += 2) {
        int s0 = g_csr[p];
        int s1 = g_csr[p + 1];
        float e00 = lrelu(g_ssrc[s0 * HH + h0] + sd0);
        float e01 = lrelu(g_ssrc[s0 * HH + h1] + sd1);
        float e10 = lrelu(g_ssrc[s1 * HH + h0] + sd0);
        float e11 = lrelu(g_ssrc[s1 * HH + h1] + sd1);
        float v00 = h[s0 * DD + lane];
        float v01 = h[s0 * DD + lane + 32];
        float v10 = h[s1 * DD + lane];
        float v11 = h[s1 * DD + lane + 32];
        a0 = fmaf(__expf(e00 - m0) * i0v, v00, a0);
        a1 = fmaf(__expf(e01 - m1) * i1v, v01, a1);
        a0 = fmaf(__expf(e10 - m0) * i0v, v10, a0);
        a1 = fmaf(__expf(e11 - m1) * i1v, v11, a1);
    }
    if (p < end) {
        int s0 = g_csr[p];
        float e00 = lrelu(g_ssrc[s0 * HH + h0] + sd0);
        float e01 = lrelu(g_ssrc[s0 * HH + h1] + sd1);
        a0 = fmaf(__expf(e00 - m0) * i0v, h[s0 * DD + lane], a0);
        a1 = fmaf(__expf(e01 - m1) * i1v, h[s0 * DD + lane + 32], a1);
    }

    outp[gw * DD + lane]      = a0 + bias[lane];
    outp[gw * DD + lane + 32] = a1 + bias[lane + 32];
}

// ---------------- launcher ----------------
extern "C" void kernel_launch(void* const* d_in, const int* in_sizes, int n_in,
                              void* d_out, int out_size) {
    const float* x    = (const float*)d_in[0];
    const void*  ei   = (const void*)d_in[1];
    const float* Ws   = (const float*)d_in[2];
    const float* asrc = (const float*)d_in[3];
    const float* adst = (const float*)d_in[4];
    const float* bias = (const float*)d_in[5];
    float*       out  = (float*)d_out;

    // CSR build (per-call, deterministic work)
    detect_k<<<1, 1>>>(ei);
    zero_k<<<(NN + 255) / 256, 256>>>();
    count_k<<<(ETOT + 255) / 256, 256>>>(ei);
    scan_k<<<1, SCAN_T>>>();
    scatter_k<<<(ETOT + 255) / 256, 256>>>(ei);

    for (int l = 0; l < LL; l++) {
        proj_k<<<NN / 16, dim3(64, 4)>>>(x, Ws + l * DD * DD, (l == 0) ? 1 : 0);
        score_k<<<(NN * HH + 255) / 256, 256>>>(asrc + l * DD, adst + l * DD);
        gat_k<<<(NN * 32 + 255) / 256, 256>>>(bias + l * DD, out,
                                              (l == LL - 1) ? 1 : 0);
    }
}

// round 4
// speedup vs baseline: 1.5560x; 1.5560x over previous
#include <cuda_runtime.h>

#define NN   20000
#define EE   640000
#define ETOT (EE + NN)
#define DD   64
#define HH   8
#define LL   8

// ---------------- static scratch (no allocations allowed) ----------------
__device__ float g_cur[NN * DD];     // layer input/output ping buffer
__device__ float g_h[NN * DD];       // per-layer projection
__device__ float g_ssrc[NN * HH];
__device__ float g_sdst[NN * HH];
__device__ int   g_cnt[NN];
__device__ int   g_rowptr[NN + 1];
__device__ int   g_fill[NN];
__device__ int   g_csr[ETOT];
__device__ int   g_is64;

__device__ __forceinline__ float lrelu(float e) { return e > 0.f ? e : 0.2f * e; }

__device__ __forceinline__ int edge_at(const void* ei, int is64, int idx) {
    return is64 ? (int)((const long long*)ei)[idx] : ((const int*)ei)[idx];
}

// ---------------- init: zero counters + parallel dtype probe ----------------
// int64 data: every 8-byte word in [0, NN). int32 data viewed as int64 packs two
// indices -> >= 2^32 almost surely.
__global__ void init_k(const void* __restrict__ ei) {
    int i = blockIdx.x * blockDim.x + threadIdx.x;
    if (i < NN) g_cnt[i] = 0;
    if (blockIdx.x == 0 && threadIdx.x < 32) {
        const long long* p = (const long long*)ei;
        long long v0 = p[threadIdx.x];
        long long v1 = p[threadIdx.x + 32];
        int ok = (v0 >= 0 && v0 < NN && v1 >= 0 && v1 < NN) ? 1 : 0;
        unsigned b = __ballot_sync(0xffffffffu, ok);
        if (threadIdx.x == 0) g_is64 = (b == 0xffffffffu) ? 1 : 0;
    }
}

__global__ void count_k(const void* __restrict__ ei) {
    int e = blockIdx.x * blockDim.x + threadIdx.x;
    if (e >= ETOT) return;
    int is64 = g_is64;
    int dst = (e < EE) ? edge_at(ei, is64, EE + e) : (e - EE);
    if (dst >= 0 && dst < NN) atomicAdd(&g_cnt[dst], 1);
}

#define SCAN_T 1024
#define IPT 20   // 1024*20 = 20480 >= NN
#define SCAN_N (SCAN_T * IPT)
__global__ void scan_k() {
    extern __shared__ int s[];          // SCAN_N ints (80 KB dynamic)
    __shared__ int wsum[32];
    int t = threadIdx.x;
    // coalesced stage-in
    for (int i = t; i < SCAN_N; i += SCAN_T) s[i] = (i < NN) ? g_cnt[i] : 0;
    __syncthreads();
    int base = t * IPT;
    int loc[IPT];
    int run = 0;
#pragma unroll
    for (int i = 0; i < IPT; i++) { loc[i] = run; run += s[base + i]; }
    int lane = t & 31, w = t >> 5;
    int inc = run;
#pragma unroll
    for (int o = 1; o < 32; o <<= 1) {
        int u = __shfl_up_sync(0xffffffffu, inc, o);
        if (lane >= o) inc += u;
    }
    if (lane == 31) wsum[w] = inc;
    __syncthreads();
    if (w == 0) {
        int v = wsum[lane];
#pragma unroll
        for (int o = 1; o < 32; o <<= 1) {
            int u = __shfl_up_sync(0xffffffffu, v, o);
            if (lane >= o) v += u;
        }
        wsum[lane] = v;
    }
    __syncthreads();
    int warpoff = (w > 0) ? wsum[w - 1] : 0;
    int texcl = warpoff + inc - run;
#pragma unroll
    for (int i = 0; i < IPT; i++) s[base + i] = texcl + loc[i];
    __syncthreads();
    // coalesced stage-out
    for (int i = t; i < NN; i += SCAN_T) {
        int v = s[i];
        g_rowptr[i] = v;
        g_fill[i] = v;
    }
    if (t == 0) g_rowptr[NN] = ETOT;
}

__global__ void scatter_k(const void* __restrict__ ei) {
    int e = blockIdx.x * blockDim.x + threadIdx.x;
    if (e >= ETOT) return;
    int is64 = g_is64;
    int src, dst;
    if (e < EE) { src = edge_at(ei, is64, e); dst = edge_at(ei, is64, EE + e); }
    else        { src = e - EE;               dst = e - EE; }
    if (dst < 0 || dst >= NN || src < 0 || src >= NN) return;
    int pos = atomicAdd(&g_fill[dst], 1);
    if (pos >= 0 && pos < ETOT) g_csr[pos] = src;
}

// ---------------- per-layer: projection h = cur @ W, fused attn scores ----
// blockDim (64,4), 16 rows/block; score epilogue uses the smem h tile.
__global__ void proj_k(const float* __restrict__ x, const float* __restrict__ W,
                       const float* __restrict__ asrc, const float* __restrict__ adst,
                       int first) {
    __shared__ float sW[64 * 64];
    __shared__ float sx[16][64];
    __shared__ float sh[16][64];
    __shared__ float sA[64], sD[64];
    const float* src = first ? x : (const float*)g_cur;
    int tx = threadIdx.x, ty = threadIdx.y;
    int tid = ty * 64 + tx;
#pragma unroll
    for (int i = tid; i < 4096; i += 256) sW[i] = W[i];
    if (tid < 64) { sA[tid] = asrc[tid]; sD[tid] = adst[tid]; }
    int row0 = blockIdx.x * 16;
#pragma unroll
    for (int r = ty; r < 16; r += 4) sx[r][tx] = src[(row0 + r) * DD + tx];
    __syncthreads();
    float acc0 = 0.f, acc1 = 0.f, acc2 = 0.f, acc3 = 0.f;
#pragma unroll
    for (int k = 0; k < 64; k++) {
        float wv = sW[k * 64 + tx];
        acc0 = fmaf(sx[ty + 0][k], wv, acc0);
        acc1 = fmaf(sx[ty + 4][k], wv, acc1);
        acc2 = fmaf(sx[ty + 8][k], wv, acc2);
        acc3 = fmaf(sx[ty + 12][k], wv, acc3);
    }
    g_h[(row0 + ty + 0) * DD + tx]  = acc0;  sh[ty + 0][tx]  = acc0;
    g_h[(row0 + ty + 4) * DD + tx]  = acc1;  sh[ty + 4][tx]  = acc1;
    g_h[(row0 + ty + 8) * DD + tx]  = acc2;  sh[ty + 8][tx]  = acc2;
    g_h[(row0 + ty + 12) * DD + tx] = acc3;  sh[ty + 12][tx] = acc3;
    __syncthreads();
    // score epilogue: 16 threads per row, 4 cols each; pair = one head
    int r = tid >> 4;          // 0..15
    int t16 = tid & 15;        // cols t16*4 .. t16*4+3 (head = t16>>1)
    int c0 = t16 * 4;
    float ps = 0.f, pd = 0.f;
#pragma unroll
    for (int c = 0; c < 4; c++) {
        float v = sh[r][c0 + c];
        ps = fmaf(v, sA[c0 + c], ps);
        pd = fmaf(v, sD[c0 + c], pd);
    }
    ps += __shfl_xor_sync(0xffffffffu, ps, 1);
    pd += __shfl_xor_sync(0xffffffffu, pd, 1);
    if ((t16 & 1) == 0) {
        int n = row0 + r;
        int hd = t16 >> 1;
        g_ssrc[n * HH + hd] = ps;
        g_sdst[n * HH + hd] = pd;
    }
}

// ---------------- per-layer: softmax-aggregate, one warp per dst node -----
__global__ void __launch_bounds__(256) gat_k(const float* __restrict__ bias,
                                             float* __restrict__ ext_out,
                                             int last) {
    int gw = (blockIdx.x * blockDim.x + threadIdx.x) >> 5;
    int lane = threadIdx.x & 31;
    if (gw >= NN) return;
    float* outp = last ? ext_out : (float*)g_cur;
    int beg = g_rowptr[gw], end = g_rowptr[gw + 1];

    float4 sdA = *(const float4*)&g_sdst[gw * HH];
    float4 sdB = *(const float4*)&g_sdst[gw * HH + 4];
    float sd0 = sdA.x, sd1 = sdA.y, sd2 = sdA.z, sd3 = sdA.w;
    float sd4 = sdB.x, sd5 = sdB.y, sd6 = sdB.z, sd7 = sdB.w;

    // pass 1: raw per-head max of ssrc over neighbors (lrelu is monotone)
    float m0 = -3e38f, m1 = -3e38f, m2 = -3e38f, m3 = -3e38f;
    float m4 = -3e38f, m5 = -3e38f, m6 = -3e38f, m7 = -3e38f;
    for (int p = beg + lane; p < end; p += 32) {
        int s = g_csr[p];
        float4 a = *(const float4*)&g_ssrc[s * HH];
        float4 b = *(const float4*)&g_ssrc[s * HH + 4];
        m0 = fmaxf(m0, a.x); m1 = fmaxf(m1, a.y); m2 = fmaxf(m2, a.z); m3 = fmaxf(m3, a.w);
        m4 = fmaxf(m4, b.x); m5 = fmaxf(m5, b.y); m6 = fmaxf(m6, b.z); m7 = fmaxf(m7, b.w);
    }
#pragma unroll
    for (int o = 16; o > 0; o >>= 1) {
        m0 = fmaxf(m0, __shfl_xor_sync(0xffffffffu, m0, o));
        m1 = fmaxf(m1, __shfl_xor_sync(0xffffffffu, m1, o));
        m2 = fmaxf(m2, __shfl_xor_sync(0xffffffffu, m2, o));
        m3 = fmaxf(m3, __shfl_xor_sync(0xffffffffu, m3, o));
        m4 = fmaxf(m4, __shfl_xor_sync(0xffffffffu, m4, o));
        m5 = fmaxf(m5, __shfl_xor_sync(0xffffffffu, m5, o));
        m6 = fmaxf(m6, __shfl_xor_sync(0xffffffffu, m6, o));
        m7 = fmaxf(m7, __shfl_xor_sync(0xffffffffu, m7, o));
    }
    m0 = lrelu(m0 + sd0); m1 = lrelu(m1 + sd1); m2 = lrelu(m2 + sd2); m3 = lrelu(m3 + sd3);
    m4 = lrelu(m4 + sd4); m5 = lrelu(m5 + sd5); m6 = lrelu(m6 + sd6); m7 = lrelu(m7 + sd7);

    // pass 2: per-head exp-sums
    float z0 = 0.f, z1 = 0.f, z2 = 0.f, z3 = 0.f, z4 = 0.f, z5 = 0.f, z6 = 0.f, z7 = 0.f;
    for (int p = beg + lane; p < end; p += 32) {
        int s = g_csr[p];
        float4 a = *(const float4*)&g_ssrc[s * HH];
        float4 b = *(const float4*)&g_ssrc[s * HH + 4];
        z0 += __expf(lrelu(a.x + sd0) - m0);
        z1 += __expf(lrelu(a.y + sd1) - m1);
        z2 += __expf(lrelu(a.z + sd2) - m2);
        z3 += __expf(lrelu(a.w + sd3) - m3);
        z4 += __expf(lrelu(b.x + sd4) - m4);
        z5 += __expf(lrelu(b.y + sd5) - m5);
        z6 += __expf(lrelu(b.z + sd6) - m6);
        z7 += __expf(lrelu(b.w + sd7) - m7);
    }
#pragma unroll
    for (int o = 16; o > 0; o >>= 1) {
        z0 += __shfl_xor_sync(0xffffffffu, z0, o);
        z1 += __shfl_xor_sync(0xffffffffu, z1, o);
        z2 += __shfl_xor_sync(0xffffffffu, z2, o);
        z3 += __shfl_xor_sync(0xffffffffu, z3, o);
        z4 += __shfl_xor_sync(0xffffffffu, z4, o);
        z5 += __shfl_xor_sync(0xffffffffu, z5, o);
        z6 += __shfl_xor_sync(0xffffffffu, z6, o);
        z7 += __shfl_xor_sync(0xffffffffu, z7, o);
    }

    // per-lane head selections
    int myk = lane & 7;        // head this lane computes alpha for (groups of 4 edges)
    int hh  = lane >> 2;       // head owning output dims {2*lane, 2*lane+1}
    float mk = m0, zk = z0, sdk = sd0;
    float mh = m0, zh = z0, sdh = sd0;
#define SEL(K, M, Z, S) { if (myk == K) { mk = M; zk = Z; sdk = S; } \
                          if (hh  == K) { mh = M; zh = Z; sdh = S; } }
    SEL(1, m1, z1, sd1) SEL(2, m2, z2, sd2) SEL(3, m3, z3, sd3)
    SEL(4, m4, z4, sd4) SEL(5, m5, z5, sd5) SEL(6, m6, z6, sd6) SEL(7, m7, z7, sd7)
#undef SEL
    float invk = 1.f / (zk + 1e-16f);
    float invh = 1.f / (zh + 1e-16f);

    // pass 3: weighted gather, 4 edges/group; lane e*8+k computes alpha(e,k)
    float ax = 0.f, ay = 0.f;
    const float* h = (const float*)g_h;
    int p = beg;
    for (; p + 4 <= end; p += 4) {
        int s0 = g_csr[p], s1 = g_csr[p + 1], s2 = g_csr[p + 2], s3 = g_csr[p + 3];
        int se = (lane < 8) ? s0 : (lane < 16) ? s1 : (lane < 24) ? s2 : s3;
        float alpha = __expf(lrelu(g_ssrc[se * HH + myk] + sdk) - mk) * invk;
        float2 h0 = *(const float2*)&h[s0 * DD + lane * 2];
        float2 h1 = *(const float2*)&h[s1 * DD + lane * 2];
        float2 h2 = *(const float2*)&h[s2 * DD + lane * 2];
        float2 h3 = *(const float2*)&h[s3 * DD + lane * 2];
        float a0 = __shfl_sync(0xffffffffu, alpha, hh);
        float a1 = __shfl_sync(0xffffffffu, alpha, 8 + hh);
        float a2 = __shfl_sync(0xffffffffu, alpha, 16 + hh);
        float a3 = __shfl_sync(0xffffffffu, alpha, 24 + hh);
        ax = fmaf(a0, h0.x, ax); ay = fmaf(a0, h0.y, ay);
        ax = fmaf(a1, h1.x, ax); ay = fmaf(a1, h1.y, ay);
        ax = fmaf(a2, h2.x, ax); ay = fmaf(a2, h2.y, ay);
        ax = fmaf(a3, h3.x, ax); ay = fmaf(a3, h3.y, ay);
    }
    for (; p < end; p++) {
        int s = g_csr[p];
        float alpha = __expf(lrelu(g_ssrc[s * HH + hh] + sdh) - mh) * invh;
        float2 hv = *(const float2*)&h[s * DD + lane * 2];
        ax = fmaf(alpha, hv.x, ax); ay = fmaf(alpha, hv.y, ay);
    }

    float2 bv = *(const float2*)&bias[lane * 2];
    float2 o2; o2.x = ax + bv.x; o2.y = ay + bv.y;
    *(float2*)&outp[gw * DD + lane * 2] = o2;
}

// ---------------- launcher ----------------
extern "C" void kernel_launch(void* const* d_in, const int* in_sizes, int n_in,
                              void* d_out, int out_size) {
    const float* x    = (const float*)d_in[0];
    const void*  ei   = (const void*)d_in[1];
    const float* Ws   = (const float*)d_in[2];
    const float* asrc = (const float*)d_in[3];
    const float* adst = (const float*)d_in[4];
    const float* bias = (const float*)d_in[5];
    float*       out  = (float*)d_out;

    static int smem_set = 0;
    if (!smem_set) {
        cudaFuncSetAttribute(scan_k, cudaFuncAttributeMaxDynamicSharedMemorySize,
                             SCAN_N * (int)sizeof(int));
        smem_set = 1;
    }

    init_k<<<(NN + 255) / 256, 256>>>(ei);
    count_k<<<(ETOT + 255) / 256, 256>>>(ei);
    scan_k<<<1, SCAN_T, SCAN_N * sizeof(int)>>>();
    scatter_k<<<(ETOT + 255) / 256, 256>>>(ei);

    for (int l = 0; l < LL; l++) {
        proj_k<<<NN / 16, dim3(64, 4)>>>(x, Ws + l * DD * DD,
                                         asrc + l * DD, adst + l * DD,
                                         (l == 0) ? 1 : 0);
        gat_k<<<(NN * 32) / 256, 256>>>(bias + l * DD, out, (l == LL - 1) ? 1 : 0);
    }
}

// round 5
// speedup vs baseline: 1.6574x; 1.0652x over previous
#include <cuda_runtime.h>

#define NN   20000
#define EE   640000
#define ETOT (EE + NN)
#define DD   64
#define HH   8
#define LL   8

// ---------------- static scratch (no allocations allowed) ----------------
__device__ float g_cur[NN * DD];     // layer input/output ping buffer
__device__ float g_h[NN * DD];       // per-layer projection
__device__ float g_ssrc[NN * HH];
__device__ float g_sdst[NN * HH];
__device__ int   g_cnt[NN];
__device__ int   g_rowptr[NN + 1];
__device__ int   g_fill[NN];
__device__ int   g_csr[ETOT];
__device__ int   g_is64;

__device__ __forceinline__ float lrelu(float e) { return e > 0.f ? e : 0.2f * e; }

__device__ __forceinline__ int edge_at(const void* ei, int is64, int idx) {
    return is64 ? (int)((const long long*)ei)[idx] : ((const int*)ei)[idx];
}

// ---------------- init: zero counters + parallel dtype probe ----------------
__global__ void init_k(const void* __restrict__ ei) {
    int i = blockIdx.x * blockDim.x + threadIdx.x;
    if (i < NN) g_cnt[i] = 0;
    if (blockIdx.x == 0 && threadIdx.x < 32) {
        const long long* p = (const long long*)ei;
        long long v0 = p[threadIdx.x];
        long long v1 = p[threadIdx.x + 32];
        int ok = (v0 >= 0 && v0 < NN && v1 >= 0 && v1 < NN) ? 1 : 0;
        unsigned b = __ballot_sync(0xffffffffu, ok);
        if (threadIdx.x == 0) g_is64 = (b == 0xffffffffu) ? 1 : 0;
    }
}

__global__ void count_k(const void* __restrict__ ei) {
    int e = blockIdx.x * blockDim.x + threadIdx.x;
    if (e >= ETOT) return;
    int is64 = g_is64;
    int dst = (e < EE) ? edge_at(ei, is64, EE + e) : (e - EE);
    if (dst >= 0 && dst < NN) atomicAdd(&g_cnt[dst], 1);
}

#define SCAN_T 1024
#define IPT 20   // 1024*20 = 20480 >= NN
#define SCAN_N (SCAN_T * IPT)
__global__ void scan_k() {
    extern __shared__ int s[];          // SCAN_N ints (80 KB dynamic)
    __shared__ int wsum[32];
    int t = threadIdx.x;
    for (int i = t; i < SCAN_N; i += SCAN_T) s[i] = (i < NN) ? g_cnt[i] : 0;
    __syncthreads();
    int base = t * IPT;
    int loc[IPT];
    int run = 0;
#pragma unroll
    for (int i = 0; i < IPT; i++) { loc[i] = run; run += s[base + i]; }
    int lane = t & 31, w = t >> 5;
    int inc = run;
#pragma unroll
    for (int o = 1; o < 32; o <<= 1) {
        int u = __shfl_up_sync(0xffffffffu, inc, o);
        if (lane >= o) inc += u;
    }
    if (lane == 31) wsum[w] = inc;
    __syncthreads();
    if (w == 0) {
        int v = wsum[lane];
#pragma unroll
        for (int o = 1; o < 32; o <<= 1) {
            int u = __shfl_up_sync(0xffffffffu, v, o);
            if (lane >= o) v += u;
        }
        wsum[lane] = v;
    }
    __syncthreads();
    int warpoff = (w > 0) ? wsum[w - 1] : 0;
    int texcl = warpoff + inc - run;
#pragma unroll
    for (int i = 0; i < IPT; i++) s[base + i] = texcl + loc[i];
    __syncthreads();
    for (int i = t; i < NN; i += SCAN_T) {
        int v = s[i];
        g_rowptr[i] = v;
        g_fill[i] = v;
    }
    if (t == 0) g_rowptr[NN] = ETOT;
}

__global__ void scatter_k(const void* __restrict__ ei) {
    int e = blockIdx.x * blockDim.x + threadIdx.x;
    if (e >= ETOT) return;
    int is64 = g_is64;
    int src, dst;
    if (e < EE) { src = edge_at(ei, is64, e); dst = edge_at(ei, is64, EE + e); }
    else        { src = e - EE;               dst = e - EE; }
    if (dst < 0 || dst >= NN || src < 0 || src >= NN) return;
    int pos = atomicAdd(&g_fill[dst], 1);
    if (pos >= 0 && pos < ETOT) g_csr[pos] = src;
}

// ---------------- per-layer: projection h = cur @ W, fused attn scores ----
__global__ void proj_k(const float* __restrict__ x, const float* __restrict__ W,
                       const float* __restrict__ asrc, const float* __restrict__ adst,
                       int first) {
    __shared__ float sW[64 * 64];
    __shared__ float sx[16][64];
    __shared__ float sh[16][64];
    __shared__ float sA[64], sD[64];
    const float* src = first ? x : (const float*)g_cur;
    int tx = threadIdx.x, ty = threadIdx.y;
    int tid = ty * 64 + tx;
#pragma unroll
    for (int i = tid; i < 4096; i += 256) sW[i] = W[i];
    if (tid < 64) { sA[tid] = asrc[tid]; sD[tid] = adst[tid]; }
    int row0 = blockIdx.x * 16;
#pragma unroll
    for (int r = ty; r < 16; r += 4) sx[r][tx] = src[(row0 + r) * DD + tx];
    __syncthreads();
    float acc0 = 0.f, acc1 = 0.f, acc2 = 0.f, acc3 = 0.f;
#pragma unroll
    for (int k = 0; k < 64; k++) {
        float wv = sW[k * 64 + tx];
        acc0 = fmaf(sx[ty + 0][k], wv, acc0);
        acc1 = fmaf(sx[ty + 4][k], wv, acc1);
        acc2 = fmaf(sx[ty + 8][k], wv, acc2);
        acc3 = fmaf(sx[ty + 12][k], wv, acc3);
    }
    g_h[(row0 + ty + 0) * DD + tx]  = acc0;  sh[ty + 0][tx]  = acc0;
    g_h[(row0 + ty + 4) * DD + tx]  = acc1;  sh[ty + 4][tx]  = acc1;
    g_h[(row0 + ty + 8) * DD + tx]  = acc2;  sh[ty + 8][tx]  = acc2;
    g_h[(row0 + ty + 12) * DD + tx] = acc3;  sh[ty + 12][tx] = acc3;
    __syncthreads();
    int r = tid >> 4;          // 0..15
    int t16 = tid & 15;        // cols t16*4 .. t16*4+3 (head = t16>>1)
    int c0 = t16 * 4;
    float ps = 0.f, pd = 0.f;
#pragma unroll
    for (int c = 0; c < 4; c++) {
        float v = sh[r][c0 + c];
        ps = fmaf(v, sA[c0 + c], ps);
        pd = fmaf(v, sD[c0 + c], pd);
    }
    ps += __shfl_xor_sync(0xffffffffu, ps, 1);
    pd += __shfl_xor_sync(0xffffffffu, pd, 1);
    if ((t16 & 1) == 0) {
        int n = row0 + r;
        int hd = t16 >> 1;
        g_ssrc[n * HH + hd] = ps;
        g_sdst[n * HH + hd] = pd;
    }
}

// ---------------- per-layer: softmax-aggregate, one warp per dst node -----
// pass 1: per-head neighbor max; pass 2 (merged): z and unnormalized weighted
// sum accumulated together, divide once at the end.
__global__ void __launch_bounds__(256) gat_k(const float* __restrict__ bias,
                                             float* __restrict__ ext_out,
                                             int last) {
    int gw = (blockIdx.x * blockDim.x + threadIdx.x) >> 5;
    int lane = threadIdx.x & 31;
    if (gw >= NN) return;
    float* outp = last ? ext_out : (float*)g_cur;
    int beg = g_rowptr[gw], end = g_rowptr[gw + 1];

    float4 sdA = *(const float4*)&g_sdst[gw * HH];
    float4 sdB = *(const float4*)&g_sdst[gw * HH + 4];
    float sd0 = sdA.x, sd1 = sdA.y, sd2 = sdA.z, sd3 = sdA.w;
    float sd4 = sdB.x, sd5 = sdB.y, sd6 = sdB.z, sd7 = sdB.w;

    // pass 1: raw per-head max of ssrc over neighbors (lrelu is monotone)
    float m0 = -3e38f, m1 = -3e38f, m2 = -3e38f, m3 = -3e38f;
    float m4 = -3e38f, m5 = -3e38f, m6 = -3e38f, m7 = -3e38f;
    for (int p = beg + lane; p < end; p += 32) {
        int s = g_csr[p];
        float4 a = *(const float4*)&g_ssrc[s * HH];
        float4 b = *(const float4*)&g_ssrc[s * HH + 4];
        m0 = fmaxf(m0, a.x); m1 = fmaxf(m1, a.y); m2 = fmaxf(m2, a.z); m3 = fmaxf(m3, a.w);
        m4 = fmaxf(m4, b.x); m5 = fmaxf(m5, b.y); m6 = fmaxf(m6, b.z); m7 = fmaxf(m7, b.w);
    }
#pragma unroll
    for (int o = 16; o > 0; o >>= 1) {
        m0 = fmaxf(m0, __shfl_xor_sync(0xffffffffu, m0, o));
        m1 = fmaxf(m1, __shfl_xor_sync(0xffffffffu, m1, o));
        m2 = fmaxf(m2, __shfl_xor_sync(0xffffffffu, m2, o));
        m3 = fmaxf(m3, __shfl_xor_sync(0xffffffffu, m3, o));
        m4 = fmaxf(m4, __shfl_xor_sync(0xffffffffu, m4, o));
        m5 = fmaxf(m5, __shfl_xor_sync(0xffffffffu, m5, o));
        m6 = fmaxf(m6, __shfl_xor_sync(0xffffffffu, m6, o));
        m7 = fmaxf(m7, __shfl_xor_sync(0xffffffffu, m7, o));
    }
    m0 = lrelu(m0 + sd0); m1 = lrelu(m1 + sd1); m2 = lrelu(m2 + sd2); m3 = lrelu(m3 + sd3);
    m4 = lrelu(m4 + sd4); m5 = lrelu(m5 + sd5); m6 = lrelu(m6 + sd6); m7 = lrelu(m7 + sd7);

    // lane roles: myk = head this lane's exp serves (edge group of 4),
    //             hh  = head owning this lane's output dims {2*lane, 2*lane+1}
    int myk = lane & 7;
    int g   = lane >> 3;       // edge slot within group (0..3)
    int hh  = lane >> 2;
    float mk = m0, sdk = sd0;
#define SELK(K, M, S) { if (myk == K) { mk = M; sdk = S; } }
    SELK(1, m1, sd1) SELK(2, m2, sd2) SELK(3, m3, sd3)
    SELK(4, m4, sd4) SELK(5, m5, sd5) SELK(6, m6, sd6) SELK(7, m7, sd7)
#undef SELK

    // merged pass: zacc (per lane, head myk) + unnormalized weighted sum
    float zacc = 0.f, ax = 0.f, ay = 0.f;
    const float* h = (const float*)g_h;
    int p = beg;
    for (; p + 4 <= end; p += 4) {
        int s0 = g_csr[p], s1 = g_csr[p + 1], s2 = g_csr[p + 2], s3 = g_csr[p + 3];
        int se = (g == 0) ? s0 : (g == 1) ? s1 : (g == 2) ? s2 : s3;
        float ev = __expf(lrelu(g_ssrc[se * HH + myk] + sdk) - mk);
        zacc += ev;
        float2 h0 = *(const float2*)&h[s0 * DD + lane * 2];
        float2 h1 = *(const float2*)&h[s1 * DD + lane * 2];
        float2 h2 = *(const float2*)&h[s2 * DD + lane * 2];
        float2 h3 = *(const float2*)&h[s3 * DD + lane * 2];
        float a0 = __shfl_sync(0xffffffffu, ev, hh);
        float a1 = __shfl_sync(0xffffffffu, ev, 8 + hh);
        float a2 = __shfl_sync(0xffffffffu, ev, 16 + hh);
        float a3 = __shfl_sync(0xffffffffu, ev, 24 + hh);
        ax = fmaf(a0, h0.x, ax); ay = fmaf(a0, h0.y, ay);
        ax = fmaf(a1, h1.x, ax); ay = fmaf(a1, h1.y, ay);
        ax = fmaf(a2, h2.x, ax); ay = fmaf(a2, h2.y, ay);
        ax = fmaf(a3, h3.x, ax); ay = fmaf(a3, h3.y, ay);
    }
    if (p < end) {
        int r = end - p;                      // 1..3, uniform across warp
        int s0 = g_csr[p];
        int s1 = (r > 1) ? g_csr[p + 1] : s0;
        int s2 = (r > 2) ? g_csr[p + 2] : s0;
        int se = (g == 0) ? s0 : (g == 1) ? s1 : (g == 2) ? s2 : s0;
        float ev = __expf(lrelu(g_ssrc[se * HH + myk] + sdk) - mk);
        if (g >= r) ev = 0.f;
        zacc += ev;
        float2 h0 = *(const float2*)&h[s0 * DD + lane * 2];
        float2 h1 = *(const float2*)&h[s1 * DD + lane * 2];
        float2 h2 = *(const float2*)&h[s2 * DD + lane * 2];
        float a0 = __shfl_sync(0xffffffffu, ev, hh);
        float a1 = __shfl_sync(0xffffffffu, ev, 8 + hh);
        float a2 = __shfl_sync(0xffffffffu, ev, 16 + hh);
        ax = fmaf(a0, h0.x, ax); ay = fmaf(a0, h0.y, ay);
        ax = fmaf(a1, h1.x, ax); ay = fmaf(a1, h1.y, ay);
        ax = fmaf(a2, h2.x, ax); ay = fmaf(a2, h2.y, ay);
    }

    // z reduction: lanes {k, k+8, k+16, k+24} share head k
    zacc += __shfl_xor_sync(0xffffffffu, zacc, 8);
    zacc += __shfl_xor_sync(0xffffffffu, zacc, 16);
    float zh = __shfl_sync(0xffffffffu, zacc, hh);   // lane 'hh' has myk==hh
    float inv = 1.f / (zh + 1e-16f);

    float2 bv = *(const float2*)&bias[lane * 2];
    float2 o2; o2.x = fmaf(ax, inv, bv.x); o2.y = fmaf(ay, inv, bv.y);
    *(float2*)&outp[gw * DD + lane * 2] = o2;
}

// ---------------- launcher ----------------
extern "C" void kernel_launch(void* const* d_in, const int* in_sizes, int n_in,
                              void* d_out, int out_size) {
    const float* x    = (const float*)d_in[0];
    const void*  ei   = (const void*)d_in[1];
    const float* Ws   = (const float*)d_in[2];
    const float* asrc = (const float*)d_in[3];
    const float* adst = (const float*)d_in[4];
    const float* bias = (const float*)d_in[5];
    float*       out  = (float*)d_out;

    static int smem_set = 0;
    if (!smem_set) {
        cudaFuncSetAttribute(scan_k, cudaFuncAttributeMaxDynamicSharedMemorySize,
                             SCAN_N * (int)sizeof(int));
        smem_set = 1;
    }

    init_k<<<(NN + 255) / 256, 256>>>(ei);
    count_k<<<(ETOT + 255) / 256, 256>>>(ei);
    scan_k<<<1, SCAN_T, SCAN_N * sizeof(int)>>>();
    scatter_k<<<(ETOT + 255) / 256, 256>>>(ei);

    for (int l = 0; l < LL; l++) {
        proj_k<<<NN / 16, dim3(64, 4)>>>(x, Ws + l * DD * DD,
                                         asrc + l * DD, adst + l * DD,
                                         (l == 0) ? 1 : 0);
        gat_k<<<(NN * 32) / 256, 256>>>(bias + l * DD, out, (l == LL - 1) ? 1 : 0);
    }
}

// round 6
// speedup vs baseline: 1.9914x; 1.2015x over previous
#include <cuda_runtime.h>

#define NN   20000
#define EE   640000
#define ETOT (EE + NN)
#define DD   64
#define HH   8
#define LL   8

// ---------------- static scratch (no allocations allowed) ----------------
__device__ float g_cur[NN * DD];
__device__ float g_h[NN * DD];
__device__ float g_ssrc[NN * HH];
__device__ float g_sdst[NN * HH];
__device__ unsigned g_smax[LL * HH];   // per-layer per-head global ssrc max (encoded)
__device__ int   g_cnt[NN];
__device__ int   g_rowptr[NN + 1];
__device__ int   g_fill[NN];
__device__ int   g_csr[ETOT];
__device__ int   g_is64;

__device__ __forceinline__ float lrelu(float e) { return e > 0.f ? e : 0.2f * e; }

__device__ __forceinline__ unsigned fenc(float f) {
    unsigned u = __float_as_uint(f);
    return (u & 0x80000000u) ? ~u : (u | 0x80000000u);
}
__device__ __forceinline__ float fdec(unsigned k) {
    return __uint_as_float((k & 0x80000000u) ? (k & 0x7FFFFFFFu) : ~k);
}

__device__ __forceinline__ int edge_at(const void* ei, int is64, int idx) {
    return is64 ? (int)((const long long*)ei)[idx] : ((const int*)ei)[idx];
}

// ---------------- init: zero counters + smax + parallel dtype probe -------
__global__ void init_k(const void* __restrict__ ei) {
    int i = blockIdx.x * blockDim.x + threadIdx.x;
    if (i < NN) g_cnt[i] = 0;
    if (i < LL * HH) g_smax[i] = 0u;          // < any finite encoded float
    if (blockIdx.x == 0 && threadIdx.x < 32) {
        const long long* p = (const long long*)ei;
        long long v0 = p[threadIdx.x];
        long long v1 = p[threadIdx.x + 32];
        int ok = (v0 >= 0 && v0 < NN && v1 >= 0 && v1 < NN) ? 1 : 0;
        unsigned b = __ballot_sync(0xffffffffu, ok);
        if (threadIdx.x == 0) g_is64 = (b == 0xffffffffu) ? 1 : 0;
    }
}

__global__ void count_k(const void* __restrict__ ei) {
    int e = blockIdx.x * blockDim.x + threadIdx.x;
    if (e >= ETOT) return;
    int is64 = g_is64;
    int dst = (e < EE) ? edge_at(ei, is64, EE + e) : (e - EE);
    if (dst >= 0 && dst < NN) atomicAdd(&g_cnt[dst], 1);
}

#define SCAN_T 1024
#define IPT 20
#define SCAN_N (SCAN_T * IPT)
__global__ void scan_k() {
    extern __shared__ int s[];
    __shared__ int wsum[32];
    int t = threadIdx.x;
    for (int i = t; i < SCAN_N; i += SCAN_T) s[i] = (i < NN) ? g_cnt[i] : 0;
    __syncthreads();
    int base = t * IPT;
    int loc[IPT];
    int run = 0;
#pragma unroll
    for (int i = 0; i < IPT; i++) { loc[i] = run; run += s[base + i]; }
    int lane = t & 31, w = t >> 5;
    int inc = run;
#pragma unroll
    for (int o = 1; o < 32; o <<= 1) {
        int u = __shfl_up_sync(0xffffffffu, inc, o);
        if (lane >= o) inc += u;
    }
    if (lane == 31) wsum[w] = inc;
    __syncthreads();
    if (w == 0) {
        int v = wsum[lane];
#pragma unroll
        for (int o = 1; o < 32; o <<= 1) {
            int u = __shfl_up_sync(0xffffffffu, v, o);
            if (lane >= o) v += u;
        }
        wsum[lane] = v;
    }
    __syncthreads();
    int warpoff = (w > 0) ? wsum[w - 1] : 0;
    int texcl = warpoff + inc - run;
#pragma unroll
    for (int i = 0; i < IPT; i++) s[base + i] = texcl + loc[i];
    __syncthreads();
    for (int i = t; i < NN; i += SCAN_T) {
        int v = s[i];
        g_rowptr[i] = v;
        g_fill[i] = v;
    }
    if (t == 0) g_rowptr[NN] = ETOT;
}

__global__ void scatter_k(const void* __restrict__ ei) {
    int e = blockIdx.x * blockDim.x + threadIdx.x;
    if (e >= ETOT) return;
    int is64 = g_is64;
    int src, dst;
    if (e < EE) { src = edge_at(ei, is64, e); dst = edge_at(ei, is64, EE + e); }
    else        { src = e - EE;               dst = e - EE; }
    if (dst < 0 || dst >= NN || src < 0 || src >= NN) return;
    int pos = atomicAdd(&g_fill[dst], 1);
    if (pos >= 0 && pos < ETOT) g_csr[pos] = src;
}

// ---------------- per-layer: projection + scores + global head max --------
__global__ void proj_k(const float* __restrict__ x, const float* __restrict__ W,
                       const float* __restrict__ asrc, const float* __restrict__ adst,
                       int first, int layer) {
    __shared__ float sW[64 * 64];
    __shared__ float sx[16][64];
    __shared__ float sh[16][64];
    __shared__ float sA[64], sD[64];
    __shared__ float sS[16][8];
    const float* src = first ? x : (const float*)g_cur;
    int tx = threadIdx.x, ty = threadIdx.y;
    int tid = ty * 64 + tx;
#pragma unroll
    for (int i = tid; i < 4096; i += 256) sW[i] = W[i];
    if (tid < 64) { sA[tid] = asrc[tid]; sD[tid] = adst[tid]; }
    int row0 = blockIdx.x * 16;
#pragma unroll
    for (int r = ty; r < 16; r += 4) sx[r][tx] = src[(row0 + r) * DD + tx];
    __syncthreads();
    float acc0 = 0.f, acc1 = 0.f, acc2 = 0.f, acc3 = 0.f;
#pragma unroll
    for (int k = 0; k < 64; k++) {
        float wv = sW[k * 64 + tx];
        acc0 = fmaf(sx[ty + 0][k], wv, acc0);
        acc1 = fmaf(sx[ty + 4][k], wv, acc1);
        acc2 = fmaf(sx[ty + 8][k], wv, acc2);
        acc3 = fmaf(sx[ty + 12][k], wv, acc3);
    }
    g_h[(row0 + ty + 0) * DD + tx]  = acc0;  sh[ty + 0][tx]  = acc0;
    g_h[(row0 + ty + 4) * DD + tx]  = acc1;  sh[ty + 4][tx]  = acc1;
    g_h[(row0 + ty + 8) * DD + tx]  = acc2;  sh[ty + 8][tx]  = acc2;
    g_h[(row0 + ty + 12) * DD + tx] = acc3;  sh[ty + 12][tx] = acc3;
    __syncthreads();
    int r = tid >> 4;
    int t16 = tid & 15;
    int c0 = t16 * 4;
    float ps = 0.f, pd = 0.f;
#pragma unroll
    for (int c = 0; c < 4; c++) {
        float v = sh[r][c0 + c];
        ps = fmaf(v, sA[c0 + c], ps);
        pd = fmaf(v, sD[c0 + c], pd);
    }
    ps += __shfl_xor_sync(0xffffffffu, ps, 1);
    pd += __shfl_xor_sync(0xffffffffu, pd, 1);
    if ((t16 & 1) == 0) {
        int n = row0 + r;
        int hd = t16 >> 1;
        g_ssrc[n * HH + hd] = ps;
        g_sdst[n * HH + hd] = pd;
        sS[r][hd] = ps;
    }
    __syncthreads();
    if (tid < HH) {
        float m = sS[0][tid];
#pragma unroll
        for (int rr = 1; rr < 16; rr++) m = fmaxf(m, sS[rr][tid]);
        atomicMax(&g_smax[layer * HH + tid], fenc(m));
    }
}

// ---------------- per-layer: single-pass softmax-aggregate ----------------
// Uses global per-head ssrc max as stability offset (valid upper bound; the
// exp scaling cancels in the final division).
__global__ void __launch_bounds__(256) gat_k(const float* __restrict__ bias,
                                             float* __restrict__ ext_out,
                                             int last, int layer) {
    int gw = (blockIdx.x * blockDim.x + threadIdx.x) >> 5;
    int lane = threadIdx.x & 31;
    if (gw >= NN) return;
    float* outp = last ? ext_out : (float*)g_cur;
    int beg = g_rowptr[gw], end = g_rowptr[gw + 1];

    int myk = lane & 7;        // head this lane's exp serves
    int g   = lane >> 3;       // edge slot within group of 4
    int hh  = lane >> 2;       // head owning output dims {2*lane, 2*lane+1}

    float sdk = g_sdst[gw * HH + myk];
    float mk  = lrelu(fdec(g_smax[layer * HH + myk]) + sdk);

    float zacc = 0.f, ax = 0.f, ay = 0.f;
    const float* h = (const float*)g_h;
    int p = beg;
    for (; p + 4 <= end; p += 4) {
        int s0 = g_csr[p], s1 = g_csr[p + 1], s2 = g_csr[p + 2], s3 = g_csr[p + 3];
        int se = (g == 0) ? s0 : (g == 1) ? s1 : (g == 2) ? s2 : s3;
        float ev = __expf(lrelu(g_ssrc[se * HH + myk] + sdk) - mk);
        zacc += ev;
        float2 h0 = *(const float2*)&h[s0 * DD + lane * 2];
        float2 h1 = *(const float2*)&h[s1 * DD + lane * 2];
        float2 h2 = *(const float2*)&h[s2 * DD + lane * 2];
        float2 h3 = *(const float2*)&h[s3 * DD + lane * 2];
        float a0 = __shfl_sync(0xffffffffu, ev, hh);
        float a1 = __shfl_sync(0xffffffffu, ev, 8 + hh);
        float a2 = __shfl_sync(0xffffffffu, ev, 16 + hh);
        float a3 = __shfl_sync(0xffffffffu, ev, 24 + hh);
        ax = fmaf(a0, h0.x, ax); ay = fmaf(a0, h0.y, ay);
        ax = fmaf(a1, h1.x, ax); ay = fmaf(a1, h1.y, ay);
        ax = fmaf(a2, h2.x, ax); ay = fmaf(a2, h2.y, ay);
        ax = fmaf(a3, h3.x, ax); ay = fmaf(a3, h3.y, ay);
    }
    if (p < end) {
        int r = end - p;                      // 1..3, uniform across warp
        int s0 = g_csr[p];
        int s1 = (r > 1) ? g_csr[p + 1] : s0;
        int s2 = (r > 2) ? g_csr[p + 2] : s0;
        int se = (g == 0) ? s0 : (g == 1) ? s1 : (g == 2) ? s2 : s0;
        float ev = __expf(lrelu(g_ssrc[se * HH + myk] + sdk) - mk);
        if (g >= r) ev = 0.f;
        zacc += ev;
        float2 h0 = *(const float2*)&h[s0 * DD + lane * 2];
        float2 h1 = *(const float2*)&h[s1 * DD + lane * 2];
        float2 h2 = *(const float2*)&h[s2 * DD + lane * 2];
        float a0 = __shfl_sync(0xffffffffu, ev, hh);
        float a1 = __shfl_sync(0xffffffffu, ev, 8 + hh);
        float a2 = __shfl_sync(0xffffffffu, ev, 16 + hh);
        ax = fmaf(a0, h0.x, ax); ay = fmaf(a0, h0.y, ay);
        ax = fmaf(a1, h1.x, ax); ay = fmaf(a1, h1.y, ay);
        ax = fmaf(a2, h2.x, ax); ay = fmaf(a2, h2.y, ay);
    }

    // z reduction: lanes {k, k+8, k+16, k+24} share head k
    zacc += __shfl_xor_sync(0xffffffffu, zacc, 8);
    zacc += __shfl_xor_sync(0xffffffffu, zacc, 16);
    float zh = __shfl_sync(0xffffffffu, zacc, hh);
    float inv = 1.f / (zh + 1e-16f);

    float2 bv = *(const float2*)&bias[lane * 2];
    float2 o2; o2.x = fmaf(ax, inv, bv.x); o2.y = fmaf(ay, inv, bv.y);
    *(float2*)&outp[gw * DD + lane * 2] = o2;
}

// ---------------- launcher ----------------
extern "C" void kernel_launch(void* const* d_in, const int* in_sizes, int n_in,
                              void* d_out, int out_size) {
    const float* x    = (const float*)d_in[0];
    const void*  ei   = (const void*)d_in[1];
    const float* Ws   = (const float*)d_in[2];
    const float* asrc = (const float*)d_in[3];
    const float* adst = (const float*)d_in[4];
    const float* bias = (const float*)d_in[5];
    float*       out  = (float*)d_out;

    static int smem_set = 0;
    if (!smem_set) {
        cudaFuncSetAttribute(scan_k, cudaFuncAttributeMaxDynamicSharedMemorySize,
                             SCAN_N * (int)sizeof(int));
        smem_set = 1;
    }

    init_k<<<(NN + 255) / 256, 256>>>(ei);
    count_k<<<(ETOT + 255) / 256, 256>>>(ei);
    scan_k<<<1, SCAN_T, SCAN_N * sizeof(int)>>>();
    scatter_k<<<(ETOT + 255) / 256, 256>>>(ei);

    for (int l = 0; l < LL; l++) {
        proj_k<<<NN / 16, dim3(64, 4)>>>(x, Ws + l * DD * DD,
                                         asrc + l * DD, adst + l * DD,
                                         (l == 0) ? 1 : 0, l);
        gat_k<<<(NN * 32) / 256, 256>>>(bias + l * DD, out,
                                        (l == LL - 1) ? 1 : 0, l);
    }
}

// round 7
// speedup vs baseline: 2.0081x; 1.0084x over previous
#include <cuda_runtime.h>

#define NN   20000
#define EE   640000
#define ETOT (EE + NN)
#define CSRMAX (EE + NN + 3 * NN)    // padded CSR upper bound (720000)
#define DD   64
#define HH   8
#define LL   8

// ---------------- static scratch (no allocations allowed) ----------------
__device__ float g_cur[NN * DD];
__device__ float g_h[NN * DD];
__device__ float g_ssrc[NN * HH];
__device__ float g_sdst[NN * HH];
__device__ unsigned g_smax[LL * HH];
__device__ int   g_cnt[NN];          // actual degree (incl. self loop)
__device__ int   g_rowptr[NN + 1];   // padded row starts (multiples of 4)
__device__ int   g_fill[NN];
__device__ int   g_csr[CSRMAX];
__device__ int   g_is64;

__device__ __forceinline__ float lrelu(float e) { return e > 0.f ? e : 0.2f * e; }

__device__ __forceinline__ unsigned fenc(float f) {
    unsigned u = __float_as_uint(f);
    return (u & 0x80000000u) ? ~u : (u | 0x80000000u);
}
__device__ __forceinline__ float fdec(unsigned k) {
    return __uint_as_float((k & 0x80000000u) ? (k & 0x7FFFFFFFu) : ~k);
}

// ---------------- init: cnt=1 (self loop), zero csr, smax, dtype probe ----
__global__ void init_k(const void* __restrict__ ei) {
    int i = blockIdx.x * blockDim.x + threadIdx.x;
    if (i < NN) g_cnt[i] = 1;                      // self loop pre-counted
    if (i < LL * HH) g_smax[i] = 0u;
    if (i * 4 < CSRMAX) *(int4*)&g_csr[i * 4] = make_int4(0, 0, 0, 0);
    if (blockIdx.x == 0 && threadIdx.x < 32) {
        const long long* p = (const long long*)ei;
        long long v0 = p[threadIdx.x];
        long long v1 = p[threadIdx.x + 32];
        int ok = (v0 >= 0 && v0 < NN && v1 >= 0 && v1 < NN) ? 1 : 0;
        unsigned b = __ballot_sync(0xffffffffu, ok);
        if (threadIdx.x == 0) g_is64 = (b == 0xffffffffu) ? 1 : 0;
    }
}

// ---------------- count: 4 edges per thread, vector loads ----------------
__global__ void count_k(const void* __restrict__ ei) {
    int t = blockIdx.x * blockDim.x + threadIdx.x;
    if (t >= EE / 4) return;
    int d0, d1, d2, d3;
    if (g_is64) {
        const longlong2* p = (const longlong2*)((const long long*)ei + EE) + t * 2;
        longlong2 a = p[0], b = p[1];
        d0 = (int)a.x; d1 = (int)a.y; d2 = (int)b.x; d3 = (int)b.y;
    } else {
        int4 a = ((const int4*)((const int*)ei + EE))[t];
        d0 = a.x; d1 = a.y; d2 = a.z; d3 = a.w;
    }
    if (d0 >= 0 && d0 < NN) atomicAdd(&g_cnt[d0], 1);
    if (d1 >= 0 && d1 < NN) atomicAdd(&g_cnt[d1], 1);
    if (d2 >= 0 && d2 < NN) atomicAdd(&g_cnt[d2], 1);
    if (d3 >= 0 && d3 < NN) atomicAdd(&g_cnt[d3], 1);
}

#define SCAN_T 1024
#define IPT 20
#define SCAN_N (SCAN_T * IPT)
__global__ void scan_k() {
    extern __shared__ int s[];
    __shared__ int wsum[32];
    int t = threadIdx.x;
    // stage in padded counts (round each row up to multiple of 4)
    for (int i = t; i < SCAN_N; i += SCAN_T)
        s[i] = (i < NN) ? ((g_cnt[i] + 3) & ~3) : 0;
    __syncthreads();
    int base = t * IPT;
    int loc[IPT];
    int run = 0;
#pragma unroll
    for (int i = 0; i < IPT; i++) { loc[i] = run; run += s[base + i]; }
    int lane = t & 31, w = t >> 5;
    int inc = run;
#pragma unroll
    for (int o = 1; o < 32; o <<= 1) {
        int u = __shfl_up_sync(0xffffffffu, inc, o);
        if (lane >= o) inc += u;
    }
    if (lane == 31) wsum[w] = inc;
    __syncthreads();
    if (w == 0) {
        int v = wsum[lane];
#pragma unroll
        for (int o = 1; o < 32; o <<= 1) {
            int u = __shfl_up_sync(0xffffffffu, v, o);
            if (lane >= o) v += u;
        }
        wsum[lane] = v;
    }
    __syncthreads();
    int warpoff = (w > 0) ? wsum[w - 1] : 0;
    int texcl = warpoff + inc - run;
#pragma unroll
    for (int i = 0; i < IPT; i++) s[base + i] = texcl + loc[i];
    __syncthreads();
    for (int i = t; i < NN; i += SCAN_T) {
        int v = s[i];
        g_rowptr[i] = v;
        g_fill[i] = v;
    }
    if (t == 0) g_rowptr[NN] = CSRMAX;
}

// ---------------- scatter: 4 edges per thread + self-loop tail ------------
__global__ void scatter_k(const void* __restrict__ ei) {
    int t = blockIdx.x * blockDim.x + threadIdx.x;
    if (t < EE / 4) {
        int s0, s1, s2, s3, d0, d1, d2, d3;
        if (g_is64) {
            const longlong2* ps = (const longlong2*)((const long long*)ei) + t * 2;
            const longlong2* pd = (const longlong2*)((const long long*)ei + EE) + t * 2;
            longlong2 a = ps[0], b = ps[1];
            longlong2 c = pd[0], d = pd[1];
            s0 = (int)a.x; s1 = (int)a.y; s2 = (int)b.x; s3 = (int)b.y;
            d0 = (int)c.x; d1 = (int)c.y; d2 = (int)d.x; d3 = (int)d.y;
        } else {
            int4 a = ((const int4*)((const int*)ei))[t];
            int4 c = ((const int4*)((const int*)ei + EE))[t];
            s0 = a.x; s1 = a.y; s2 = a.z; s3 = a.w;
            d0 = c.x; d1 = c.y; d2 = c.z; d3 = c.w;
        }
        if (d0 >= 0 && d0 < NN && s0 >= 0 && s0 < NN) { int p = atomicAdd(&g_fill[d0], 1); if (p >= 0 && p < CSRMAX) g_csr[p] = s0; }
        if (d1 >= 0 && d1 < NN && s1 >= 0 && s1 < NN) { int p = atomicAdd(&g_fill[d1], 1); if (p >= 0 && p < CSRMAX) g_csr[p] = s1; }
        if (d2 >= 0 && d2 < NN && s2 >= 0 && s2 < NN) { int p = atomicAdd(&g_fill[d2], 1); if (p >= 0 && p < CSRMAX) g_csr[p] = s2; }
        if (d3 >= 0 && d3 < NN && s3 >= 0 && s3 < NN) { int p = atomicAdd(&g_fill[d3], 1); if (p >= 0 && p < CSRMAX) g_csr[p] = s3; }
    } else {
        int n = t - EE / 4;
        if (n < NN) {
            int p = atomicAdd(&g_fill[n], 1);
            if (p >= 0 && p < CSRMAX) g_csr[p] = n;
        }
    }
}

// ---------------- per-layer: projection + scores + global head max --------
__global__ void proj_k(const float* __restrict__ x, const float* __restrict__ W,
                       const float* __restrict__ asrc, const float* __restrict__ adst,
                       int first, int layer) {
    __shared__ float sW[64 * 64];
    __shared__ float sx[16][64];
    __shared__ float sh[16][64];
    __shared__ float sA[64], sD[64];
    __shared__ float sS[16][8];
    const float* src = first ? x : (const float*)g_cur;
    int tx = threadIdx.x, ty = threadIdx.y;
    int tid = ty * 64 + tx;
#pragma unroll
    for (int i = tid; i < 4096; i += 256) sW[i] = W[i];
    if (tid < 64) { sA[tid] = asrc[tid]; sD[tid] = adst[tid]; }
    int row0 = blockIdx.x * 16;
#pragma unroll
    for (int r = ty; r < 16; r += 4) sx[r][tx] = src[(row0 + r) * DD + tx];
    __syncthreads();
    float acc0 = 0.f, acc1 = 0.f, acc2 = 0.f, acc3 = 0.f;
#pragma unroll
    for (int k = 0; k < 64; k++) {
        float wv = sW[k * 64 + tx];
        acc0 = fmaf(sx[ty + 0][k], wv, acc0);
        acc1 = fmaf(sx[ty + 4][k], wv, acc1);
        acc2 = fmaf(sx[ty + 8][k], wv, acc2);
        acc3 = fmaf(sx[ty + 12][k], wv, acc3);
    }
    g_h[(row0 + ty + 0) * DD + tx]  = acc0;  sh[ty + 0][tx]  = acc0;
    g_h[(row0 + ty + 4) * DD + tx]  = acc1;  sh[ty + 4][tx]  = acc1;
    g_h[(row0 + ty + 8) * DD + tx]  = acc2;  sh[ty + 8][tx]  = acc2;
    g_h[(row0 + ty + 12) * DD + tx] = acc3;  sh[ty + 12][tx] = acc3;
    __syncthreads();
    int r = tid >> 4;
    int t16 = tid & 15;
    int c0 = t16 * 4;
    float ps = 0.f, pd = 0.f;
#pragma unroll
    for (int c = 0; c < 4; c++) {
        float v = sh[r][c0 + c];
        ps = fmaf(v, sA[c0 + c], ps);
        pd = fmaf(v, sD[c0 + c], pd);
    }
    ps += __shfl_xor_sync(0xffffffffu, ps, 1);
    pd += __shfl_xor_sync(0xffffffffu, pd, 1);
    if ((t16 & 1) == 0) {
        int n = row0 + r;
        int hd = t16 >> 1;
        g_ssrc[n * HH + hd] = ps;
        g_sdst[n * HH + hd] = pd;
        sS[r][hd] = ps;
    }
    __syncthreads();
    if (tid < HH) {
        float m = sS[0][tid];
#pragma unroll
        for (int rr = 1; rr < 16; rr++) m = fmaxf(m, sS[rr][tid]);
        atomicMax(&g_smax[layer * HH + tid], fenc(m));
    }
}

// ---------------- per-layer: single-pass softmax-aggregate ----------------
__global__ void __launch_bounds__(256) gat_k(const float* __restrict__ bias,
                                             float* __restrict__ ext_out,
                                             int last, int layer) {
    int gw = (blockIdx.x * blockDim.x + threadIdx.x) >> 5;
    int lane = threadIdx.x & 31;
    if (gw >= NN) return;
    float* outp = last ? ext_out : (float*)g_cur;
    int beg = g_rowptr[gw];
    int cnt = g_cnt[gw];
    int ngr = (cnt + 3) >> 2;

    int myk = lane & 7;        // head this lane's exp serves
    int g   = lane >> 3;       // edge slot within group of 4
    int hh  = lane >> 2;       // head owning output dims {2*lane, 2*lane+1}

    float sdk = g_sdst[gw * HH + myk];
    float mk  = lrelu(fdec(g_smax[layer * HH + myk]) + sdk);

    float zacc = 0.f, ax = 0.f, ay = 0.f;
    const float* h = (const float*)g_h;
    const int4* csr4 = (const int4*)&g_csr[beg];

    int4 s4 = csr4[0];
    for (int q = 0; q < ngr; q++) {
        int4 nxt = (q + 1 < ngr) ? csr4[q + 1] : s4;
        int s0 = s4.x, s1 = s4.y, s2 = s4.z, s3 = s4.w;
        int se = (g == 0) ? s0 : (g == 1) ? s1 : (g == 2) ? s2 : s3;
        float ev = __expf(lrelu(g_ssrc[se * HH + myk] + sdk) - mk);
        int rem = cnt - q * 4;
        if (g >= rem) ev = 0.f;                 // mask padded slots (last group only)
        zacc += ev;
        float2 h0 = *(const float2*)&h[s0 * DD + lane * 2];
        float2 h1 = *(const float2*)&h[s1 * DD + lane * 2];
        float2 h2 = *(const float2*)&h[s2 * DD + lane * 2];
        float2 h3 = *(const float2*)&h[s3 * DD + lane * 2];
        float a0 = __shfl_sync(0xffffffffu, ev, hh);
        float a1 = __shfl_sync(0xffffffffu, ev, 8 + hh);
        float a2 = __shfl_sync(0xffffffffu, ev, 16 + hh);
        float a3 = __shfl_sync(0xffffffffu, ev, 24 + hh);
        ax = fmaf(a0, h0.x, ax); ay = fmaf(a0, h0.y, ay);
        ax = fmaf(a1, h1.x, ax); ay = fmaf(a1, h1.y, ay);
        ax = fmaf(a2, h2.x, ax); ay = fmaf(a2, h2.y, ay);
        ax = fmaf(a3, h3.x, ax); ay = fmaf(a3, h3.y, ay);
        s4 = nxt;
    }

    // z reduction: lanes {k, k+8, k+16, k+24} share head k
    zacc += __shfl_xor_sync(0xffffffffu, zacc, 8);
    zacc += __shfl_xor_sync(0xffffffffu, zacc, 16);
    float zh = __shfl_sync(0xffffffffu, zacc, hh);
    float inv = 1.f / (zh + 1e-16f);

    float2 bv = *(const float2*)&bias[lane * 2];
    float2 o2; o2.x = fmaf(ax, inv, bv.x); o2.y = fmaf(ay, inv, bv.y);
    *(float2*)&outp[gw * DD + lane * 2] = o2;
}

// ---------------- launcher ----------------
extern "C" void kernel_launch(void* const* d_in, const int* in_sizes, int n_in,
                              void* d_out, int out_size) {
    const float* x    = (const float*)d_in[0];
    const void*  ei   = (const void*)d_in[1];
    const float* Ws   = (const float*)d_in[2];
    const float* asrc = (const float*)d_in[3];
    const float* adst = (const float*)d_in[4];
    const float* bias = (const float*)d_in[5];
    float*       out  = (float*)d_out;

    static int smem_set = 0;
    if (!smem_set) {
        cudaFuncSetAttribute(scan_k, cudaFuncAttributeMaxDynamicSharedMemorySize,
                             SCAN_N * (int)sizeof(int));
        smem_set = 1;
    }

    int init_threads = CSRMAX / 4;                       // covers NN and LL*HH too
    init_k<<<(init_threads + 255) / 256, 256>>>(ei);
    count_k<<<(EE / 4 + 255) / 256, 256>>>(ei);
    scan_k<<<1, SCAN_T, SCAN_N * sizeof(int)>>>();
    scatter_k<<<(EE / 4 + NN + 255) / 256, 256>>>(ei);

    for (int l = 0; l < LL; l++) {
        proj_k<<<NN / 16, dim3(64, 4)>>>(x, Ws + l * DD * DD,
                                         asrc + l * DD, adst + l * DD,
                                         (l == 0) ? 1 : 0, l);
        gat_k<<<(NN * 32) / 256, 256>>>(bias + l * DD, out,
                                        (l == LL - 1) ? 1 : 0, l);
    }
}

// round 8
// speedup vs baseline: 2.0737x; 1.0327x over previous
#include <cuda_runtime.h>

#define NN   20000
#define EE   640000
#define ETOT (EE + NN)
#define CSRMAX (EE + NN + 3 * NN)
#define DD   64
#define HH   8
#define LL   8

// ---------------- static scratch (no allocations allowed) ----------------
__device__ float g_cur[NN * DD];
__device__ float g_h[NN * DD];
__device__ float g_ssrc[NN * HH];
__device__ float g_sdst[NN * HH];
__device__ unsigned g_smax[LL * HH];
__device__ int   g_cnt[NN];
__device__ int   g_rowptr[NN + 1];
__device__ int   g_fill[NN];
__device__ int   g_csr[CSRMAX];
__device__ int   g_is64;

__device__ __forceinline__ float lrelu(float e) { return e > 0.f ? e : 0.2f * e; }

__device__ __forceinline__ unsigned fenc(float f) {
    unsigned u = __float_as_uint(f);
    return (u & 0x80000000u) ? ~u : (u | 0x80000000u);
}
__device__ __forceinline__ float fdec(unsigned k) {
    return __uint_as_float((k & 0x80000000u) ? (k & 0x7FFFFFFFu) : ~k);
}

// ---------------- init ----------------
__global__ void init_k(const void* __restrict__ ei) {
    int i = blockIdx.x * blockDim.x + threadIdx.x;
    if (i < NN) g_cnt[i] = 1;
    if (i < LL * HH) g_smax[i] = 0u;
    if (i * 4 < CSRMAX) *(int4*)&g_csr[i * 4] = make_int4(0, 0, 0, 0);
    if (blockIdx.x == 0 && threadIdx.x < 32) {
        const long long* p = (const long long*)ei;
        long long v0 = p[threadIdx.x];
        long long v1 = p[threadIdx.x + 32];
        int ok = (v0 >= 0 && v0 < NN && v1 >= 0 && v1 < NN) ? 1 : 0;
        unsigned b = __ballot_sync(0xffffffffu, ok);
        if (threadIdx.x == 0) g_is64 = (b == 0xffffffffu) ? 1 : 0;
    }
}

__global__ void count_k(const void* __restrict__ ei) {
    int t = blockIdx.x * blockDim.x + threadIdx.x;
    if (t >= EE / 4) return;
    int d0, d1, d2, d3;
    if (g_is64) {
        const longlong2* p = (const longlong2*)((const long long*)ei + EE) + t * 2;
        longlong2 a = p[0], b = p[1];
        d0 = (int)a.x; d1 = (int)a.y; d2 = (int)b.x; d3 = (int)b.y;
    } else {
        int4 a = ((const int4*)((const int*)ei + EE))[t];
        d0 = a.x; d1 = a.y; d2 = a.z; d3 = a.w;
    }
    if (d0 >= 0 && d0 < NN) atomicAdd(&g_cnt[d0], 1);
    if (d1 >= 0 && d1 < NN) atomicAdd(&g_cnt[d1], 1);
    if (d2 >= 0 && d2 < NN) atomicAdd(&g_cnt[d2], 1);
    if (d3 >= 0 && d3 < NN) atomicAdd(&g_cnt[d3], 1);
}

#define SCAN_T 1024
#define IPT 20
#define SCAN_N (SCAN_T * IPT)
__global__ void scan_k() {
    extern __shared__ int s[];
    __shared__ int wsum[32];
    int t = threadIdx.x;
    for (int i = t; i < SCAN_N; i += SCAN_T)
        s[i] = (i < NN) ? ((g_cnt[i] + 3) & ~3) : 0;
    __syncthreads();
    int base = t * IPT;
    int loc[IPT];
    int run = 0;
#pragma unroll
    for (int i = 0; i < IPT; i++) { loc[i] = run; run += s[base + i]; }
    int lane = t & 31, w = t >> 5;
    int inc = run;
#pragma unroll
    for (int o = 1; o < 32; o <<= 1) {
        int u = __shfl_up_sync(0xffffffffu, inc, o);
        if (lane >= o) inc += u;
    }
    if (lane == 31) wsum[w] = inc;
    __syncthreads();
    if (w == 0) {
        int v = wsum[lane];
#pragma unroll
        for (int o = 1; o < 32; o <<= 1) {
            int u = __shfl_up_sync(0xffffffffu, v, o);
            if (lane >= o) v += u;
        }
        wsum[lane] = v;
    }
    __syncthreads();
    int warpoff = (w > 0) ? wsum[w - 1] : 0;
    int texcl = warpoff + inc - run;
#pragma unroll
    for (int i = 0; i < IPT; i++) s[base + i] = texcl + loc[i];
    __syncthreads();
    for (int i = t; i < NN; i += SCAN_T) {
        int v = s[i];
        g_rowptr[i] = v;
        g_fill[i] = v;
    }
    if (t == 0) g_rowptr[NN] = CSRMAX;
}

__global__ void scatter_k(const void* __restrict__ ei) {
    int t = blockIdx.x * blockDim.x + threadIdx.x;
    if (t < EE / 4) {
        int s0, s1, s2, s3, d0, d1, d2, d3;
        if (g_is64) {
            const longlong2* ps = (const longlong2*)((const long long*)ei) + t * 2;
            const longlong2* pd = (const longlong2*)((const long long*)ei + EE) + t * 2;
            longlong2 a = ps[0], b = ps[1];
            longlong2 c = pd[0], d = pd[1];
            s0 = (int)a.x; s1 = (int)a.y; s2 = (int)b.x; s3 = (int)b.y;
            d0 = (int)c.x; d1 = (int)c.y; d2 = (int)d.x; d3 = (int)d.y;
        } else {
            int4 a = ((const int4*)((const int*)ei))[t];
            int4 c = ((const int4*)((const int*)ei + EE))[t];
            s0 = a.x; s1 = a.y; s2 = a.z; s3 = a.w;
            d0 = c.x; d1 = c.y; d2 = c.z; d3 = c.w;
        }
        if (d0 >= 0 && d0 < NN && s0 >= 0 && s0 < NN) { int p = atomicAdd(&g_fill[d0], 1); if (p >= 0 && p < CSRMAX) g_csr[p] = s0; }
        if (d1 >= 0 && d1 < NN && s1 >= 0 && s1 < NN) { int p = atomicAdd(&g_fill[d1], 1); if (p >= 0 && p < CSRMAX) g_csr[p] = s1; }
        if (d2 >= 0 && d2 < NN && s2 >= 0 && s2 < NN) { int p = atomicAdd(&g_fill[d2], 1); if (p >= 0 && p < CSRMAX) g_csr[p] = s2; }
        if (d3 >= 0 && d3 < NN && s3 >= 0 && s3 < NN) { int p = atomicAdd(&g_fill[d3], 1); if (p >= 0 && p < CSRMAX) g_csr[p] = s3; }
    } else {
        int n = t - EE / 4;
        if (n < NN) {
            int p = atomicAdd(&g_fill[n], 1);
            if (p >= 0 && p < CSRMAX) g_csr[p] = n;
        }
    }
}

// ---------------- per-layer: projection + scores + global head max --------
__global__ void proj_k(const float* __restrict__ x, const float* __restrict__ W,
                       const float* __restrict__ asrc, const float* __restrict__ adst,
                       int first, int layer) {
    __shared__ float sW[64 * 64];
    __shared__ float sx[16][64];
    __shared__ float sh[16][64];
    __shared__ float sA[64], sD[64];
    __shared__ float sS[16][8];
    const float* src = first ? x : (const float*)g_cur;
    int tx = threadIdx.x, ty = threadIdx.y;
    int tid = ty * 64 + tx;
#pragma unroll
    for (int i = tid; i < 4096; i += 256) sW[i] = W[i];
    if (tid < 64) { sA[tid] = asrc[tid]; sD[tid] = adst[tid]; }
    int row0 = blockIdx.x * 16;
#pragma unroll
    for (int r = ty; r < 16; r += 4) sx[r][tx] = src[(row0 + r) * DD + tx];
    __syncthreads();
    float acc0 = 0.f, acc1 = 0.f, acc2 = 0.f, acc3 = 0.f;
#pragma unroll
    for (int k = 0; k < 64; k++) {
        float wv = sW[k * 64 + tx];
        acc0 = fmaf(sx[ty + 0][k], wv, acc0);
        acc1 = fmaf(sx[ty + 4][k], wv, acc1);
        acc2 = fmaf(sx[ty + 8][k], wv, acc2);
        acc3 = fmaf(sx[ty + 12][k], wv, acc3);
    }
    g_h[(row0 + ty + 0) * DD + tx]  = acc0;  sh[ty + 0][tx]  = acc0;
    g_h[(row0 + ty + 4) * DD + tx]  = acc1;  sh[ty + 4][tx]  = acc1;
    g_h[(row0 + ty + 8) * DD + tx]  = acc2;  sh[ty + 8][tx]  = acc2;
    g_h[(row0 + ty + 12) * DD + tx] = acc3;  sh[ty + 12][tx] = acc3;
    __syncthreads();
    int r = tid >> 4;
    int t16 = tid & 15;
    int c0 = t16 * 4;
    float ps = 0.f, pd = 0.f;
#pragma unroll
    for (int c = 0; c < 4; c++) {
        float v = sh[r][c0 + c];
        ps = fmaf(v, sA[c0 + c], ps);
        pd = fmaf(v, sD[c0 + c], pd);
    }
    ps += __shfl_xor_sync(0xffffffffu, ps, 1);
    pd += __shfl_xor_sync(0xffffffffu, pd, 1);
    if ((t16 & 1) == 0) {
        int n = row0 + r;
        int hd = t16 >> 1;
        g_ssrc[n * HH + hd] = ps;
        g_sdst[n * HH + hd] = pd;
        sS[r][hd] = ps;
    }
    __syncthreads();
    if (tid < HH) {
        float m = sS[0][tid];
#pragma unroll
        for (int rr = 1; rr < 16; rr++) m = fmaxf(m, sS[rr][tid]);
        atomicMax(&g_smax[layer * HH + tid], fenc(m));
    }
}

// ---------------- per-layer: single-pass softmax-aggregate ----------------
// Lane roles: myk = lane&7 (head whose exp this lane computes, edge slot lane>>3),
// half = lane>>4 (0: edge slots {0,2}, 1: slots {1,3}),
// c4 = lane&15 (output dims c4*4..c4*4+3, head hsel = c4>>1).
__global__ void __launch_bounds__(256) gat_k(const float* __restrict__ bias,
                                             float* __restrict__ ext_out,
                                             int last, int layer) {
    int gw = (blockIdx.x * blockDim.x + threadIdx.x) >> 5;
    int lane = threadIdx.x & 31;
    if (gw >= NN) return;
    float* outp = last ? ext_out : (float*)g_cur;
    int beg = g_rowptr[gw];
    int cnt = g_cnt[gw];
    int ngr = (cnt + 3) >> 2;

    int myk  = lane & 7;
    int g    = lane >> 3;
    int half = lane >> 4;
    int c4   = lane & 15;
    int hsel = c4 >> 1;

    float sdk = g_sdst[gw * HH + myk];
    float mk  = lrelu(fdec(g_smax[layer * HH + myk]) + sdk);

    int la = (half ? 8 : 0) + hsel;      // alpha source lane, first owned slot
    int lb = (half ? 24 : 16) + hsel;    // alpha source lane, second owned slot

    float zacc = 0.f;
    float ax = 0.f, ay = 0.f, az = 0.f, aw = 0.f;
    const float* h = (const float*)g_h;
    const int4* csr4 = (const int4*)&g_csr[beg];

    int4 s4 = csr4[0];
    for (int q = 0; q < ngr; q++) {
        int4 nxt = (q + 1 < ngr) ? csr4[q + 1] : s4;
        int se = (g == 0) ? s4.x : (g == 1) ? s4.y : (g == 2) ? s4.z : s4.w;
        float ev = __expf(lrelu(g_ssrc[se * HH + myk] + sdk) - mk);
        int rem = cnt - q * 4;
        if (g >= rem) ev = 0.f;
        zacc += ev;
        int ea = half ? s4.y : s4.x;     // owned slots: half0 -> {0,2}, half1 -> {1,3}
        int eb = half ? s4.w : s4.z;
        float4 ha = *(const float4*)&h[ea * DD + c4 * 4];
        float4 hb = *(const float4*)&h[eb * DD + c4 * 4];
        float aa = __shfl_sync(0xffffffffu, ev, la);
        float ab = __shfl_sync(0xffffffffu, ev, lb);
        ax = fmaf(aa, ha.x, ax); ay = fmaf(aa, ha.y, ay);
        az = fmaf(aa, ha.z, az); aw = fmaf(aa, ha.w, aw);
        ax = fmaf(ab, hb.x, ax); ay = fmaf(ab, hb.y, ay);
        az = fmaf(ab, hb.z, az); aw = fmaf(ab, hb.w, aw);
        s4 = nxt;
    }

    // combine halves (each dim group accumulated in lanes c4 and c4+16)
    ax += __shfl_xor_sync(0xffffffffu, ax, 16);
    ay += __shfl_xor_sync(0xffffffffu, ay, 16);
    az += __shfl_xor_sync(0xffffffffu, az, 16);
    aw += __shfl_xor_sync(0xffffffffu, aw, 16);

    // z reduction: after xor8+xor16, lane i holds z of head i&7
    zacc += __shfl_xor_sync(0xffffffffu, zacc, 8);
    zacc += __shfl_xor_sync(0xffffffffu, zacc, 16);
    float zh = __shfl_sync(0xffffffffu, zacc, hsel);
    float inv = 1.f / (zh + 1e-16f);

    if (lane < 16) {
        float4 bv = *(const float4*)&bias[c4 * 4];
        float4 o4;
        o4.x = fmaf(ax, inv, bv.x);
        o4.y = fmaf(ay, inv, bv.y);
        o4.z = fmaf(az, inv, bv.z);
        o4.w = fmaf(aw, inv, bv.w);
        *(float4*)&outp[gw * DD + c4 * 4] = o4;
    }
}

// ---------------- launcher ----------------
extern "C" void kernel_launch(void* const* d_in, const int* in_sizes, int n_in,
                              void* d_out, int out_size) {
    const float* x    = (const float*)d_in[0];
    const void*  ei   = (const void*)d_in[1];
    const float* Ws   = (const float*)d_in[2];
    const float* asrc = (const float*)d_in[3];
    const float* adst = (const float*)d_in[4];
    const float* bias = (const float*)d_in[5];
    float*       out  = (float*)d_out;

    static int smem_set = 0;
    if (!smem_set) {
        cudaFuncSetAttribute(scan_k, cudaFuncAttributeMaxDynamicSharedMemorySize,
                             SCAN_N * (int)sizeof(int));
        smem_set = 1;
    }

    int init_threads = CSRMAX / 4;
    init_k<<<(init_threads + 255) / 256, 256>>>(ei);
    count_k<<<(EE / 4 + 255) / 256, 256>>>(ei);
    scan_k<<<1, SCAN_T, SCAN_N * sizeof(int)>>>();
    scatter_k<<<(EE / 4 + NN + 255) / 256, 256>>>(ei);

    for (int l = 0; l < LL; l++) {
        proj_k<<<NN / 16, dim3(64, 4)>>>(x, Ws + l * DD * DD,
                                         asrc + l * DD, adst + l * DD,
                                         (l == 0) ? 1 : 0, l);
        gat_k<<<(NN * 32) / 256, 256>>>(bias + l * DD, out,
                                        (l == LL - 1) ? 1 : 0, l);
    }
}